// round 2
// baseline (speedup 1.0000x reference)
#include <cuda_runtime.h>
#include <cstddef>

#define NN 50000
#define FD 128
#define NE 600000

// Scratch (device globals — no allocation allowed)
__device__ float g_h1[NN * FD];
__device__ float g_h2[NN * FD];
__device__ float g_msum[NN * FD];
__device__ float g_deg[NN];
__device__ float g_invdeg[NN];

// ---------------- zero / degree kernels ----------------

__global__ void zero_msum_kernel() {
    int i = blockIdx.x * blockDim.x + threadIdx.x;
    if (i < NN * FD) g_msum[i] = 0.f;
}

__global__ void zero_deg_kernel() {
    int i = blockIdx.x * blockDim.x + threadIdx.x;
    if (i < NN) g_deg[i] = 0.f;
}

__global__ void deg_kernel(const int* __restrict__ dst) {
    int e = blockIdx.x * blockDim.x + threadIdx.x;
    if (e < NE) atomicAdd(&g_deg[dst[e]], 1.0f);
}

__global__ void invdeg_kernel() {
    int i = blockIdx.x * blockDim.x + threadIdx.x;
    if (i < NN) g_invdeg[i] = 1.0f / fmaxf(g_deg[i], 1.0f);
}

// ---------------- edge scatter (mean-agg numerator) ----------------
// One warp per edge; each lane moves 4 floats via vectorized red.global.

__global__ void scatter_kernel(const float* __restrict__ h,
                               const int* __restrict__ src,
                               const int* __restrict__ dst) {
    int gw = (blockIdx.x * blockDim.x + threadIdx.x) >> 5;
    int lane = threadIdx.x & 31;
    if (gw >= NE) return;
    int s = __ldg(src + gw);
    int d = __ldg(dst + gw);
    const float4* hin = (const float4*)(h + (size_t)s * FD);
    float4 v = hin[lane];
    float* p = g_msum + (size_t)d * FD + lane * 4;
    asm volatile("red.global.add.v4.f32 [%0], {%1, %2, %3, %4};"
                 :: "l"(p), "f"(v.x), "f"(v.y), "f"(v.z), "f"(v.w)
                 : "memory");
}

// ---------------- fused dual-GEMM + bias + relu ----------------
// out[row, j] = act( sum_k h[row,k]*Ws[k,j] + (msum[row,k]*invdeg[row])*Wn[k,j] + b[j] )
// Block: 16 rows x 128 cols, 128 threads. Each thread: 4 rows x 4 cols.
// k tiled by 32. smem: 2x(32x128) weights + 2x(16x32) activations = 36 KB.

__global__ void __launch_bounds__(128)
fused_sage_kernel(const float* __restrict__ h,
                  const float* __restrict__ Ws,
                  const float* __restrict__ Wn,
                  const float* __restrict__ bias,
                  float* __restrict__ out,
                  int fout, int do_relu) {
    __shared__ float s_ws[32][128];
    __shared__ float s_wn[32][128];
    __shared__ float s_h[16][32];
    __shared__ float s_hn[16][32];

    const int tid = threadIdx.x;
    const int tj = tid & 31;   // col group: cols 4*tj .. 4*tj+3
    const int tr = tid >> 5;   // row group: rows 4*tr .. 4*tr+3
    const int row0 = blockIdx.x * 16;

    float acc[4][4];
#pragma unroll
    for (int c = 0; c < 4; ++c) {
        int j = tj * 4 + c;
        float bv = (j < fout) ? __ldg(bias + j) : 0.f;
#pragma unroll
        for (int r = 0; r < 4; ++r) acc[r][c] = bv;
    }

    for (int kt = 0; kt < 4; ++kt) {
        // load 32x128 weight tiles (thread tid = column j, i = k within tile)
#pragma unroll 8
        for (int i = 0; i < 32; ++i) {
            int k = kt * 32 + i;
            float vs = 0.f, vn = 0.f;
            if (tid < fout) {
                vs = __ldg(Ws + (size_t)k * fout + tid);
                vn = __ldg(Wn + (size_t)k * fout + tid);
            }
            s_ws[i][tid] = vs;
            s_wn[i][tid] = vn;
        }
        // load 16x32 activation tiles (h and mean-neighbor)
#pragma unroll
        for (int i = 0; i < 4; ++i) {
            int idx = tid + i * 128;
            int r = idx >> 5;
            int kk = idx & 31;
            int row = row0 + r;
            size_t off = (size_t)row * FD + kt * 32 + kk;
            s_h[r][kk] = h[off];
            s_hn[r][kk] = g_msum[off] * g_invdeg[row];
        }
        __syncthreads();

#pragma unroll
        for (int k = 0; k < 32; ++k) {
            float4 ws = *(const float4*)&s_ws[k][tj * 4];
            float4 wn = *(const float4*)&s_wn[k][tj * 4];
#pragma unroll
            for (int r = 0; r < 4; ++r) {
                float a  = s_h[tr * 4 + r][k];
                float an = s_hn[tr * 4 + r][k];
                acc[r][0] = fmaf(a, ws.x, acc[r][0]);
                acc[r][0] = fmaf(an, wn.x, acc[r][0]);
                acc[r][1] = fmaf(a, ws.y, acc[r][1]);
                acc[r][1] = fmaf(an, wn.y, acc[r][1]);
                acc[r][2] = fmaf(a, ws.z, acc[r][2]);
                acc[r][2] = fmaf(an, wn.z, acc[r][2]);
                acc[r][3] = fmaf(a, ws.w, acc[r][3]);
                acc[r][3] = fmaf(an, wn.w, acc[r][3]);
            }
        }
        __syncthreads();
    }

#pragma unroll
    for (int r = 0; r < 4; ++r) {
        int row = row0 + tr * 4 + r;
#pragma unroll
        for (int c = 0; c < 4; ++c) {
            int j = tj * 4 + c;
            if (j < fout) {
                float v = acc[r][c];
                if (do_relu) v = fmaxf(v, 0.f);
                out[(size_t)row * fout + j] = v;
            }
        }
    }
}

// ---------------- launch ----------------

extern "C" void kernel_launch(void* const* d_in, const int* in_sizes, int n_in,
                              void* d_out, int out_size) {
    const float* x   = (const float*)d_in[0];
    const int*   src = (const int*)d_in[1];
    const int*   dst = (const int*)d_in[2];
    const float* Ws0 = (const float*)d_in[3];
    const float* Wn0 = (const float*)d_in[4];
    const float* b0  = (const float*)d_in[5];
    const float* Ws1 = (const float*)d_in[6];
    const float* Wn1 = (const float*)d_in[7];
    const float* b1  = (const float*)d_in[8];
    const float* Ws2 = (const float*)d_in[9];
    const float* Wn2 = (const float*)d_in[10];
    const float* b2  = (const float*)d_in[11];
    float* out = (float*)d_out;

    float *h1, *h2;
    cudaGetSymbolAddress((void**)&h1, g_h1);
    cudaGetSymbolAddress((void**)&h2, g_h2);

    const int ZB = 256;
    const int zero_msum_grid = (NN * FD + ZB - 1) / ZB;
    const int node_grid = (NN + ZB - 1) / ZB;
    const int edge_grid = (NE + ZB - 1) / ZB;
    const int scat_grid = (NE * 32 + ZB - 1) / ZB;   // one warp per edge
    const int gemm_grid = NN / 16;                   // 50000 / 16 = 3125 exactly

    // degree (shared by all layers)
    zero_deg_kernel<<<node_grid, ZB>>>();
    deg_kernel<<<edge_grid, ZB>>>(dst);
    invdeg_kernel<<<node_grid, ZB>>>();

    // layer 0: x -> h1 (relu)
    zero_msum_kernel<<<zero_msum_grid, ZB>>>();
    scatter_kernel<<<scat_grid, ZB>>>(x, src, dst);
    fused_sage_kernel<<<gemm_grid, 128>>>(x, Ws0, Wn0, b0, h1, 128, 1);

    // layer 1: h1 -> h2 (relu)
    zero_msum_kernel<<<zero_msum_grid, ZB>>>();
    scatter_kernel<<<scat_grid, ZB>>>(h1, src, dst);
    fused_sage_kernel<<<gemm_grid, 128>>>(h1, Ws1, Wn1, b1, h2, 128, 1);

    // layer 2: h2 -> out (no relu, fout=47)
    zero_msum_kernel<<<zero_msum_grid, ZB>>>();
    scatter_kernel<<<scat_grid, ZB>>>(h2, src, dst);
    fused_sage_kernel<<<gemm_grid, 128>>>(h2, Ws2, Wn2, b2, out, 47, 0);
}